// round 8
// baseline (speedup 1.0000x reference)
#include <cuda_runtime.h>
#include <cuda_fp16.h>

#define V      100000
#define VP     100096              // 391 * 256, padded
#define H      300
#define LL     64
#define B      64
#define G3     900
#define KP     320                 // padded K staged for A (20 x 16)
#define NCHUNK 19                  // only 19 chunks carry data (k < 304)
#define NTILE  256
#define NBLK   391
#define SA_STR 328                 // halfs; A row stride (R3-proven)
#define WST    24                  // halfs; W row stride (R3-proven)

// pass-1 smem layout (bytes)
#define SA_BYTES (64 * SA_STR * 2)          // 41984
#define SW_OFF   SA_BYTES
#define WBUFB    (256 * WST * 2)            // 12288 per slot
#define P1_SMEM  (SW_OFF + 2 * WBUFB)       // 66560

// ---------------- device state ----------------
__device__ float d_h0[B * H];
__device__ float d_h1[B * H];
__device__ float d_gi[B * G3];
__device__ float d_gh[B * G3];
__device__ float d_gi_all[LL * B * G3];
__device__ float d_Wt[4][300 * 1024];
__device__ __half d_Whi[(size_t)NCHUNK * VP * 16];   // [kc][v][16] chunked
__device__ __half d_hhi[B * KP];
__device__ __half d_alog[(size_t)B * VP];            // approx logits
__device__ int    d_ids[B];

__device__ __forceinline__ unsigned long long umax64(unsigned long long a, unsigned long long b) {
    return a > b ? a : b;
}
__device__ __forceinline__ unsigned mono32(float x) {
    unsigned u = __float_as_uint(x);
    return (u & 0x80000000u) ? ~u : (u | 0x80000000u);
}
__device__ __forceinline__ unsigned long long pack_key(float x, int v) {
    return ((unsigned long long)mono32(x) << 32) |
           (unsigned long long)(0xFFFFFFFFu - (unsigned)v);
}
__device__ __forceinline__ unsigned cvta_s(const void* p) {
    return (unsigned)__cvta_generic_to_shared(p);
}

// ---------------- init ----------------
__global__ void init_k() {
    int i = blockIdx.x * 256 + threadIdx.x;
    if (i < B * H) d_h0[i] = 0.f;
    if (i < B * KP) d_hhi[i] = __float2half(0.f);
    if (i < B) d_ids[i] = 0;
}

// ---------------- prep: out_W -> fp16, chunked [kc][v][16], VP-padded ----------------
__global__ void prep_w(const float* __restrict__ outW) {
    size_t i = (size_t)blockIdx.x * 256 + threadIdx.x;
    if (i >= (size_t)NCHUNK * VP * 16) return;
    int kk = (int)(i & 15);
    size_t r = i >> 4;
    int v = (int)(r % VP);
    int kc = (int)(r / VP);
    int k = kc * 16 + kk;
    float w = (v < V && k < H) ? outW[(size_t)v * H + k] : 0.f;
    d_Whi[i] = __float2half(w);
}

// ---------------- prep: transpose GRU weights to [k][n-padded-1024] ----------------
__global__ void prep_wt(const float* __restrict__ a, const float* __restrict__ b,
                        const float* __restrict__ c, const float* __restrict__ d) {
    int z = blockIdx.y;
    const float* src = (z == 0) ? a : (z == 1) ? b : (z == 2) ? c : d;
    int i = blockIdx.x * 256 + threadIdx.x;
    if (i >= 300 * 1024) return;
    int k = i >> 10, n = i & 1023;
    d_Wt[z][i] = (n < G3) ? src[n * H + k] : 0.f;
}

// ---------------- encoder: gi for ALL timesteps (16 rows/block) ----------------
__global__ void enc_gi_all(const int* __restrict__ input, const float* __restrict__ emb) {
    __shared__ float xs[16][304];
    __shared__ int ids16[16];
    int row0 = blockIdx.y * 16;
    int tid = threadIdx.x;
    if (tid < 16) {
        int row = row0 + tid;
        ids16[tid] = input[(row >> 6) * B + (row & 63)];
    }
    __syncthreads();
    for (int idx = tid; idx < 16 * H; idx += 256) {
        int r = idx / H, k = idx - r * H;
        xs[r][k] = emb[(size_t)ids16[r] * H + k];
    }
    __syncthreads();
    int slot = tid & 63, rg = tid >> 6;
    int n = blockIdx.x * 256 + slot * 4;
    const float* W = d_Wt[0];
    float4 acc[4];
    #pragma unroll
    for (int r = 0; r < 4; r++) acc[r] = make_float4(0.f, 0.f, 0.f, 0.f);
    for (int k0 = 0; k0 < H; k0 += 4) {
        const float* wp = W + (size_t)k0 * 1024 + n;
        float4 w0 = *(const float4*)(wp);
        float4 w1 = *(const float4*)(wp + 1024);
        float4 w2 = *(const float4*)(wp + 2048);
        float4 w3 = *(const float4*)(wp + 3072);
        #pragma unroll
        for (int r = 0; r < 4; r++) {
            float4 hx = *(const float4*)&xs[rg * 4 + r][k0];
            acc[r].x += hx.x * w0.x + hx.y * w1.x + hx.z * w2.x + hx.w * w3.x;
            acc[r].y += hx.x * w0.y + hx.y * w1.y + hx.z * w2.y + hx.w * w3.y;
            acc[r].z += hx.x * w0.z + hx.y * w1.z + hx.z * w2.z + hx.w * w3.z;
            acc[r].w += hx.x * w0.w + hx.y * w1.w + hx.z * w2.w + hx.w * w3.w;
        }
    }
    if (n < G3) {
        #pragma unroll
        for (int r = 0; r < 4; r++)
            *(float4*)&d_gi_all[(size_t)(row0 + rg * 4 + r) * G3 + n] = acc[r];
    }
}

// ---------------- per-step encoder gh ----------------
__global__ void enc_gh(int p) {
    __shared__ float xs[4][304];
    const float* h = p ? d_h1 : d_h0;
    int b0 = blockIdx.y * 4;
    int tid = threadIdx.x;
    for (int idx = tid; idx < 4 * H; idx += 256) {
        int r = idx / H, k = idx - r * H;
        xs[r][k] = h[(b0 + r) * H + k];
    }
    __syncthreads();
    int slot = tid & 63, bl = tid >> 6;
    int n = blockIdx.x * 256 + slot * 4;
    const float* W = d_Wt[1];
    const float* xr = xs[bl];
    float4 acc = make_float4(0.f, 0.f, 0.f, 0.f);
    for (int k0 = 0; k0 < H; k0 += 4) {
        float4 hx = *(const float4*)(xr + k0);
        const float* wp = W + (size_t)k0 * 1024 + n;
        float4 w0 = *(const float4*)(wp);
        float4 w1 = *(const float4*)(wp + 1024);
        float4 w2 = *(const float4*)(wp + 2048);
        float4 w3 = *(const float4*)(wp + 3072);
        acc.x += hx.x * w0.x + hx.y * w1.x + hx.z * w2.x + hx.w * w3.x;
        acc.y += hx.x * w0.y + hx.y * w1.y + hx.z * w2.y + hx.w * w3.y;
        acc.z += hx.x * w0.z + hx.y * w1.z + hx.z * w2.z + hx.w * w3.z;
        acc.w += hx.x * w0.w + hx.y * w1.w + hx.z * w2.w + hx.w * w3.w;
    }
    if (n < G3) *(float4*)&d_gh[(b0 + bl) * G3 + n] = acc;
}

// ---------------- per-step decoder GEMMs ----------------
__global__ void dec_gemm(const float* __restrict__ emb, int p) {
    __shared__ float xs[4][304];
    __shared__ int ids4[4];
    int z = blockIdx.z;
    int b0 = blockIdx.y * 4;
    int tid = threadIdx.x;
    if (z == 0) {
        if (tid < 4) ids4[tid] = d_ids[b0 + tid];
        __syncthreads();
        for (int idx = tid; idx < 4 * H; idx += 256) {
            int r = idx / H, k = idx - r * H;
            xs[r][k] = fmaxf(emb[(size_t)ids4[r] * H + k], 0.f);
        }
    } else {
        const float* h = p ? d_h1 : d_h0;
        for (int idx = tid; idx < 4 * H; idx += 256) {
            int r = idx / H, k = idx - r * H;
            xs[r][k] = h[(b0 + r) * H + k];
        }
    }
    __syncthreads();
    int slot = tid & 63, bl = tid >> 6;
    int n = blockIdx.x * 256 + slot * 4;
    const float* W = d_Wt[z == 0 ? 2 : 3];
    const float* xr = xs[bl];
    float4 acc = make_float4(0.f, 0.f, 0.f, 0.f);
    for (int k0 = 0; k0 < H; k0 += 4) {
        float4 hx = *(const float4*)(xr + k0);
        const float* wp = W + (size_t)k0 * 1024 + n;
        float4 w0 = *(const float4*)(wp);
        float4 w1 = *(const float4*)(wp + 1024);
        float4 w2 = *(const float4*)(wp + 2048);
        float4 w3 = *(const float4*)(wp + 3072);
        acc.x += hx.x * w0.x + hx.y * w1.x + hx.z * w2.x + hx.w * w3.x;
        acc.y += hx.x * w0.y + hx.y * w1.y + hx.z * w2.y + hx.w * w3.y;
        acc.z += hx.x * w0.z + hx.y * w1.z + hx.z * w2.z + hx.w * w3.z;
        acc.w += hx.x * w0.w + hx.y * w1.w + hx.z * w2.w + hx.w * w3.w;
    }
    float* out = z ? d_gh : d_gi;
    if (n < G3) *(float4*)&out[(b0 + bl) * G3 + n] = acc;
}

// ---------------- GRU combine (+ optional fp16 round of new h) ----------------
__global__ void combine_k(int use_all, int t, const float* __restrict__ bih,
                          const float* __restrict__ bhh, int p, int split) {
    int i = blockIdx.x * 256 + threadIdx.x;
    if (i >= B * H) return;
    int b = i / H, k = i - b * H;
    const float* h_in = p ? d_h1 : d_h0;
    float* h_out = p ? d_h0 : d_h1;
    const float* gib = (use_all ? d_gi_all + (size_t)t * B * G3 : d_gi) + b * G3;
    const float* ghb = d_gh + b * G3;

    float sr  = gib[k]         + bih[k]         + ghb[k]         + bhh[k];
    float sz  = gib[H + k]     + bih[H + k]     + ghb[H + k]     + bhh[H + k];
    float in_ = gib[2 * H + k] + bih[2 * H + k];
    float hn  = ghb[2 * H + k] + bhh[2 * H + k];

    float r = 1.f / (1.f + expf(-sr));
    float z = 1.f / (1.f + expf(-sz));
    float nn = tanhf(in_ + r * hn);
    float hv = (1.f - z) * nn + z * h_in[i];
    h_out[i] = hv;
    if (split) d_hhi[b * KP + k] = __float2half(hv);
}

// ================= logits pass 1: single fp16 mma, fp16 accumulate =================
__device__ __forceinline__ void ldsm_x4(unsigned* r, unsigned a) {
    asm volatile("ldmatrix.sync.aligned.m8n8.x4.shared.b16 {%0,%1,%2,%3}, [%4];"
        : "=r"(r[0]), "=r"(r[1]), "=r"(r[2]), "=r"(r[3]) : "r"(a));
}
__device__ __forceinline__ void mma_16816_h(unsigned* c, const unsigned* a, const unsigned* b) {
    asm volatile("mma.sync.aligned.m16n8k16.row.col.f16.f16.f16.f16 "
        "{%0,%1}, {%2,%3,%4,%5}, {%6,%7}, {%0,%1};"
        : "+r"(c[0]), "+r"(c[1])
        : "r"(a[0]), "r"(a[1]), "r"(a[2]), "r"(a[3]), "r"(b[0]), "r"(b[1]));
}
__device__ __forceinline__ void cp16(unsigned d, const void* s) {
    asm volatile("cp.async.cg.shared.global [%0], [%1], 16;" :: "r"(d), "l"(s));
}

__device__ __forceinline__ void load_W(unsigned sb, int kc, int slot, int v0, int tid) {
    const __half* g = d_Whi + ((size_t)kc * VP + v0) * 16;
    unsigned dst = sb + SW_OFF + slot * WBUFB;
    #pragma unroll
    for (int r = 0; r < 2; r++) {
        int t = tid + r * 256;
        int row = t >> 1, hf = t & 1;
        cp16(dst + row * (WST * 2) + hf * 16, g + (size_t)row * 16 + hf * 8);
    }
}

__global__ void __launch_bounds__(256, 3)
logits1_k(const float* __restrict__ outb) {
    extern __shared__ __align__(16) char smem[];
    unsigned sb = cvta_s(smem);
    __half* sA = (__half*)smem;
    int tid = threadIdx.x, warp = tid >> 5, lane = tid & 31;
    int v0 = blockIdx.x * NTILE;

    load_W(sb, 0, 0, v0, tid);
    asm volatile("cp.async.commit_group;" ::: "memory");

    // stage A (h fp16) 64 x 320 halfs, row stride SA_STR
    for (int i = tid; i < 64 * (KP / 8); i += 256) {
        int b = i / (KP / 8), q = i - b * (KP / 8);
        uint4 val = ((const uint4*)d_hhi)[(size_t)b * (KP / 8) + q];
        *(uint4*)(sA + b * SA_STR + q * 8) = val;
    }

    unsigned acc[4][4][2];
    #pragma unroll
    for (int mi = 0; mi < 4; mi++)
        #pragma unroll
        for (int nt = 0; nt < 4; nt++) { acc[mi][nt][0] = 0u; acc[mi][nt][1] = 0u; }

    int buf = 0;
    for (int c = 0; c < NCHUNK; c++) {
        if (c + 1 < NCHUNK) {
            load_W(sb, c + 1, buf ^ 1, v0, tid);
            asm volatile("cp.async.commit_group;" ::: "memory");
            asm volatile("cp.async.wait_group 1;" ::: "memory");
        } else {
            asm volatile("cp.async.wait_group 0;" ::: "memory");
        }
        __syncthreads();

        int k0 = c * 16;
        unsigned a[4][4];
        #pragma unroll
        for (int mi = 0; mi < 4; mi++) {
            int rowA = mi * 16 + (lane & 15);
            int colA = k0 + ((lane >> 4) << 3);
            ldsm_x4(a[mi], sb + (rowA * SA_STR + colA) * 2);
        }
        unsigned wbase = sb + SW_OFF + buf * WBUFB;
        unsigned bf[2][4];
        #pragma unroll
        for (int pr = 0; pr < 2; pr++) {
            int rowB = warp * 32 + pr * 16 + ((lane & 7) | (((lane >> 4) & 1) << 3));
            int colB = ((lane >> 3) & 1) * 8;
            ldsm_x4(bf[pr], wbase + (rowB * WST + colB) * 2);
        }
        #pragma unroll
        for (int mi = 0; mi < 4; mi++)
            #pragma unroll
            for (int pr = 0; pr < 2; pr++) {
                mma_16816_h(acc[mi][pr * 2 + 0], a[mi], &bf[pr][0]);
                mma_16816_h(acc[mi][pr * 2 + 1], a[mi], &bf[pr][2]);
            }
        __syncthreads();
        buf ^= 1;
    }

    // ---- epilogue: bias + fp16 stores of approx logits ----
    // fp16-acc fragment: acc[..][0] = half2(c0,c1) for row r1; acc[..][1] same for r2.
    int wn = warp * 32;
    #pragma unroll
    for (int nt = 0; nt < 4; nt++) {
        int v = v0 + wn + nt * 8 + (lane & 3) * 2;
        float bias0 = (v < V)     ? outb[v]     : -1e4f;
        float bias1 = (v + 1 < V) ? outb[v + 1] : -1e4f;
        #pragma unroll
        for (int mi = 0; mi < 4; mi++) {
            int r1 = mi * 16 + (lane >> 2);
            int r2 = r1 + 8;
            float2 lo = __half22float2(*(__half2*)&acc[mi][nt][0]);
            float2 hi = __half22float2(*(__half2*)&acc[mi][nt][1]);
            float f00 = lo.x + bias0, f01 = lo.y + bias1;
            float f10 = hi.x + bias0, f11 = hi.y + bias1;
            *(__half2*)(d_alog + (size_t)r1 * VP + v) = __floats2half2_rn(f00, f01);
            *(__half2*)(d_alog + (size_t)r2 * VP + v) = __floats2half2_rn(f10, f11);
        }
    }
}

// ================= logits pass 2: one block per batch row =================
__global__ void __launch_bounds__(512, 2)
scan_k(const float* __restrict__ outW, const float* __restrict__ outb,
       float* __restrict__ out, int t, int p) {
    __shared__ float smaxs[16];
    __shared__ unsigned long long sbest[16];
    __shared__ float hs[304];
    __shared__ float thr;
    int b = blockIdx.x;
    int tid = threadIdx.x, lane = tid & 31, warp = tid >> 5;
    const __half* arow = d_alog + (size_t)b * VP;
    const float* hrow = (p ? d_h0 : d_h1) + b * H;

    if (tid < H) hs[tid] = hrow[tid];

    // phase A: block max of stored fp16 approx logits
    float mx = -3e38f;
    for (int i = tid; i < VP / 8; i += 512) {
        uint4 pk = ((const uint4*)arow)[i];
        __half hv[8];
        *(uint4*)hv = pk;
        #pragma unroll
        for (int j = 0; j < 8; j++) mx = fmaxf(mx, __half2float(hv[j]));
    }
    #pragma unroll
    for (int o = 16; o; o >>= 1) mx = fmaxf(mx, __shfl_xor_sync(0xffffffffu, mx, o));
    if (lane == 0) smaxs[warp] = mx;
    __syncthreads();
    if (tid == 0) {
        float m2 = smaxs[0];
        #pragma unroll
        for (int w = 1; w < 16; w++) m2 = fmaxf(m2, smaxs[w]);
        thr = m2 - 0.25f;    // fp16-accumulate error bound + storage rounding
    }
    __syncthreads();
    float th = thr;

    // phase B: candidates + exact fp32 rescore
    unsigned long long best = 0ULL;
    for (int i = tid; i < VP / 8; i += 512) {
        uint4 pk = ((const uint4*)arow)[i];
        __half hv[8];
        *(uint4*)hv = pk;
        #pragma unroll
        for (int j = 0; j < 8; j++) {
            float f = __half2float(hv[j]);
            int v = i * 8 + j;
            if (f >= th && v < V) {
                float s = outb[v];
                const float* wr = outW + (size_t)v * H;
                for (int k = 0; k < H; k += 4) {
                    float4 w4 = *(const float4*)(wr + k);
                    s += hs[k] * w4.x + hs[k + 1] * w4.y + hs[k + 2] * w4.z + hs[k + 3] * w4.w;
                }
                best = umax64(best, pack_key(s, v));
            }
        }
    }
    #pragma unroll
    for (int o = 16; o; o >>= 1) best = umax64(best, __shfl_xor_sync(0xffffffffu, best, o));
    if (lane == 0) sbest[warp] = best;
    __syncthreads();
    if (tid == 0) {
        unsigned long long m = sbest[0];
        #pragma unroll
        for (int w = 1; w < 16; w++) m = umax64(m, sbest[w]);
        int idx = (int)(0xFFFFFFFFu - (unsigned)(m & 0xFFFFFFFFULL));
        d_ids[b] = idx;
        out[t * B + b] = (float)idx;
    }
}

// ---------------- launch ----------------
extern "C" void kernel_launch(void* const* d_in, const int* in_sizes, int n_in,
                              void* d_out, int out_size)
{
    const int*   input = (const int*)  d_in[0];
    const float* emb   = (const float*)d_in[1];
    const float* eWih  = (const float*)d_in[2];
    const float* eWhh  = (const float*)d_in[3];
    const float* ebih  = (const float*)d_in[4];
    const float* ebhh  = (const float*)d_in[5];
    const float* dWih  = (const float*)d_in[6];
    const float* dWhh  = (const float*)d_in[7];
    const float* dbih  = (const float*)d_in[8];
    const float* dbhh  = (const float*)d_in[9];
    const float* outW  = (const float*)d_in[10];
    const float* outb  = (const float*)d_in[11];
    float* out = (float*)d_out;

    cudaFuncSetAttribute(logits1_k, cudaFuncAttributeMaxDynamicSharedMemorySize, P1_SMEM);

    init_k<<<(B * KP + 255) / 256, 256>>>();
    {
        size_t tot = (size_t)NCHUNK * VP * 16;
        prep_w<<<(int)((tot + 255) / 256), 256>>>(outW);
    }
    prep_wt<<<dim3(1200, 4), 256>>>(eWih, eWhh, dWih, dWhh);
    enc_gi_all<<<dim3(4, 256), 256>>>(input, emb);

    // ---- encoder ----
    for (int t = 0; t < LL; t++) {
        int p = t & 1;
        enc_gh<<<dim3(4, 16), 256>>>(p);
        combine_k<<<(B * H + 255) / 256, 256>>>(1, t, ebih, ebhh, p, 0);
    }
    // ---- decoder ----
    for (int t = 0; t < LL; t++) {
        int p = t & 1;
        dec_gemm<<<dim3(4, 16, 2), 256>>>(emb, p);
        combine_k<<<(B * H + 255) / 256, 256>>>(0, 0, dbih, dbhh, p, 1);
        logits1_k<<<NBLK, 256, P1_SMEM>>>(outb);
        scan_k<<<B, 512>>>(outW, outb, out, t, p);
    }
}

// round 9
// speedup vs baseline: 3.8095x; 3.8095x over previous
#include <cuda_runtime.h>
#include <cuda_fp16.h>

#define V      100000
#define VP     100096              // 1564 units * 64
#define H      300
#define LL     64
#define B      64
#define G3     900
#define KP     320                 // padded K staged for A (20 x 16)
#define NCHUNK 19                  // only 19 chunks carry data (k < 304)
#define NBLK   296                 // exactly 2 blocks per SM
#define NUMAX  6                   // max units (of 64 cols) per block
#define SA_STR 328                 // halfs; A row stride (proven)
#define WST    24                  // halfs; W row stride (proven)

// pass-1 smem layout (bytes)
#define SA_BYTES (64 * SA_STR * 2)          // 41984
#define SW_OFF   SA_BYTES
#define WBUFB    (NUMAX * 64 * WST * 2)     // 18432 per slot
#define P1_SMEM  (SW_OFF + 2 * WBUFB)       // 78848

// ---------------- device state ----------------
__device__ float d_h0[B * H];
__device__ float d_h1[B * H];
__device__ float d_gi[B * G3];
__device__ float d_gh[B * G3];
__device__ float d_gi_all[LL * B * G3];
__device__ float d_Wt[4][300 * 1024];
__device__ __half d_Whi[(size_t)NCHUNK * VP * 16];   // [kc][v][16] chunked
__device__ __half d_hhi[B * KP];
__device__ __half d_alog[(size_t)B * VP];            // approx logits
__device__ int    d_ids[B];

__device__ __forceinline__ unsigned long long umax64(unsigned long long a, unsigned long long b) {
    return a > b ? a : b;
}
__device__ __forceinline__ unsigned mono32(float x) {
    unsigned u = __float_as_uint(x);
    return (u & 0x80000000u) ? ~u : (u | 0x80000000u);
}
__device__ __forceinline__ unsigned long long pack_key(float x, int v) {
    return ((unsigned long long)mono32(x) << 32) |
           (unsigned long long)(0xFFFFFFFFu - (unsigned)v);
}
__device__ __forceinline__ unsigned cvta_s(const void* p) {
    return (unsigned)__cvta_generic_to_shared(p);
}

// ---------------- init ----------------
__global__ void init_k() {
    int i = blockIdx.x * 256 + threadIdx.x;
    if (i < B * H) d_h0[i] = 0.f;
    if (i < B * KP) d_hhi[i] = __float2half(0.f);
    if (i < B) d_ids[i] = 0;
}

// ---------------- prep: out_W -> fp16, chunked [kc][v][16], VP-padded ----------------
__global__ void prep_w(const float* __restrict__ outW) {
    size_t i = (size_t)blockIdx.x * 256 + threadIdx.x;
    if (i >= (size_t)NCHUNK * VP * 16) return;
    int kk = (int)(i & 15);
    size_t r = i >> 4;
    int v = (int)(r % VP);
    int kc = (int)(r / VP);
    int k = kc * 16 + kk;
    float w = (v < V && k < H) ? outW[(size_t)v * H + k] : 0.f;
    d_Whi[i] = __float2half(w);
}

// ---------------- prep: transpose GRU weights to [k][n-padded-1024] ----------------
__global__ void prep_wt(const float* __restrict__ a, const float* __restrict__ b,
                        const float* __restrict__ c, const float* __restrict__ d) {
    int z = blockIdx.y;
    const float* src = (z == 0) ? a : (z == 1) ? b : (z == 2) ? c : d;
    int i = blockIdx.x * 256 + threadIdx.x;
    if (i >= 300 * 1024) return;
    int k = i >> 10, n = i & 1023;
    d_Wt[z][i] = (n < G3) ? src[n * H + k] : 0.f;
}

// ---------------- encoder: gi for ALL timesteps (16 rows/block) ----------------
__global__ void enc_gi_all(const int* __restrict__ input, const float* __restrict__ emb) {
    __shared__ float xs[16][304];
    __shared__ int ids16[16];
    int row0 = blockIdx.y * 16;
    int tid = threadIdx.x;
    if (tid < 16) {
        int row = row0 + tid;
        ids16[tid] = input[(row >> 6) * B + (row & 63)];
    }
    __syncthreads();
    for (int idx = tid; idx < 16 * H; idx += 256) {
        int r = idx / H, k = idx - r * H;
        xs[r][k] = emb[(size_t)ids16[r] * H + k];
    }
    __syncthreads();
    int slot = tid & 63, rg = tid >> 6;
    int n = blockIdx.x * 256 + slot * 4;
    const float* W = d_Wt[0];
    float4 acc[4];
    #pragma unroll
    for (int r = 0; r < 4; r++) acc[r] = make_float4(0.f, 0.f, 0.f, 0.f);
    for (int k0 = 0; k0 < H; k0 += 4) {
        const float* wp = W + (size_t)k0 * 1024 + n;
        float4 w0 = *(const float4*)(wp);
        float4 w1 = *(const float4*)(wp + 1024);
        float4 w2 = *(const float4*)(wp + 2048);
        float4 w3 = *(const float4*)(wp + 3072);
        #pragma unroll
        for (int r = 0; r < 4; r++) {
            float4 hx = *(const float4*)&xs[rg * 4 + r][k0];
            acc[r].x += hx.x * w0.x + hx.y * w1.x + hx.z * w2.x + hx.w * w3.x;
            acc[r].y += hx.x * w0.y + hx.y * w1.y + hx.z * w2.y + hx.w * w3.y;
            acc[r].z += hx.x * w0.z + hx.y * w1.z + hx.z * w2.z + hx.w * w3.z;
            acc[r].w += hx.x * w0.w + hx.y * w1.w + hx.z * w2.w + hx.w * w3.w;
        }
    }
    if (n < G3) {
        #pragma unroll
        for (int r = 0; r < 4; r++)
            *(float4*)&d_gi_all[(size_t)(row0 + rg * 4 + r) * G3 + n] = acc[r];
    }
}

// ---------------- per-step encoder gh ----------------
__global__ void enc_gh(int p) {
    __shared__ float xs[4][304];
    const float* h = p ? d_h1 : d_h0;
    int b0 = blockIdx.y * 4;
    int tid = threadIdx.x;
    for (int idx = tid; idx < 4 * H; idx += 256) {
        int r = idx / H, k = idx - r * H;
        xs[r][k] = h[(b0 + r) * H + k];
    }
    __syncthreads();
    int slot = tid & 63, bl = tid >> 6;
    int n = blockIdx.x * 256 + slot * 4;
    const float* W = d_Wt[1];
    const float* xr = xs[bl];
    float4 acc = make_float4(0.f, 0.f, 0.f, 0.f);
    for (int k0 = 0; k0 < H; k0 += 4) {
        float4 hx = *(const float4*)(xr + k0);
        const float* wp = W + (size_t)k0 * 1024 + n;
        float4 w0 = *(const float4*)(wp);
        float4 w1 = *(const float4*)(wp + 1024);
        float4 w2 = *(const float4*)(wp + 2048);
        float4 w3 = *(const float4*)(wp + 3072);
        acc.x += hx.x * w0.x + hx.y * w1.x + hx.z * w2.x + hx.w * w3.x;
        acc.y += hx.x * w0.y + hx.y * w1.y + hx.z * w2.y + hx.w * w3.y;
        acc.z += hx.x * w0.z + hx.y * w1.z + hx.z * w2.z + hx.w * w3.z;
        acc.w += hx.x * w0.w + hx.y * w1.w + hx.z * w2.w + hx.w * w3.w;
    }
    if (n < G3) *(float4*)&d_gh[(b0 + bl) * G3 + n] = acc;
}

// ---------------- per-step decoder GEMMs ----------------
__global__ void dec_gemm(const float* __restrict__ emb, int p) {
    __shared__ float xs[4][304];
    __shared__ int ids4[4];
    int z = blockIdx.z;
    int b0 = blockIdx.y * 4;
    int tid = threadIdx.x;
    if (z == 0) {
        if (tid < 4) ids4[tid] = d_ids[b0 + tid];
        __syncthreads();
        for (int idx = tid; idx < 4 * H; idx += 256) {
            int r = idx / H, k = idx - r * H;
            xs[r][k] = fmaxf(emb[(size_t)ids4[r] * H + k], 0.f);
        }
    } else {
        const float* h = p ? d_h1 : d_h0;
        for (int idx = tid; idx < 4 * H; idx += 256) {
            int r = idx / H, k = idx - r * H;
            xs[r][k] = h[(b0 + r) * H + k];
        }
    }
    __syncthreads();
    int slot = tid & 63, bl = tid >> 6;
    int n = blockIdx.x * 256 + slot * 4;
    const float* W = d_Wt[z == 0 ? 2 : 3];
    const float* xr = xs[bl];
    float4 acc = make_float4(0.f, 0.f, 0.f, 0.f);
    for (int k0 = 0; k0 < H; k0 += 4) {
        float4 hx = *(const float4*)(xr + k0);
        const float* wp = W + (size_t)k0 * 1024 + n;
        float4 w0 = *(const float4*)(wp);
        float4 w1 = *(const float4*)(wp + 1024);
        float4 w2 = *(const float4*)(wp + 2048);
        float4 w3 = *(const float4*)(wp + 3072);
        acc.x += hx.x * w0.x + hx.y * w1.x + hx.z * w2.x + hx.w * w3.x;
        acc.y += hx.x * w0.y + hx.y * w1.y + hx.z * w2.y + hx.w * w3.y;
        acc.z += hx.x * w0.z + hx.y * w1.z + hx.z * w2.z + hx.w * w3.z;
        acc.w += hx.x * w0.w + hx.y * w1.w + hx.z * w2.w + hx.w * w3.w;
    }
    float* out = z ? d_gh : d_gi;
    if (n < G3) *(float4*)&out[(b0 + bl) * G3 + n] = acc;
}

// ---------------- GRU combine (+ optional fp16 round of new h) ----------------
__global__ void combine_k(int use_all, int t, const float* __restrict__ bih,
                          const float* __restrict__ bhh, int p, int split) {
    int i = blockIdx.x * 256 + threadIdx.x;
    if (i >= B * H) return;
    int b = i / H, k = i - b * H;
    const float* h_in = p ? d_h1 : d_h0;
    float* h_out = p ? d_h0 : d_h1;
    const float* gib = (use_all ? d_gi_all + (size_t)t * B * G3 : d_gi) + b * G3;
    const float* ghb = d_gh + b * G3;

    float sr  = gib[k]         + bih[k]         + ghb[k]         + bhh[k];
    float sz  = gib[H + k]     + bih[H + k]     + ghb[H + k]     + bhh[H + k];
    float in_ = gib[2 * H + k] + bih[2 * H + k];
    float hn  = ghb[2 * H + k] + bhh[2 * H + k];

    float r = 1.f / (1.f + expf(-sr));
    float z = 1.f / (1.f + expf(-sz));
    float nn = tanhf(in_ + r * hn);
    float hv = (1.f - z) * nn + z * h_in[i];
    h_out[i] = hv;
    if (split) d_hhi[b * KP + k] = __float2half(hv);
}

// ================= logits pass 1: fp16 mma, f32 acc, variable-width tiles =================
__device__ __forceinline__ void ldsm_x4(unsigned* r, unsigned a) {
    asm volatile("ldmatrix.sync.aligned.m8n8.x4.shared.b16 {%0,%1,%2,%3}, [%4];"
        : "=r"(r[0]), "=r"(r[1]), "=r"(r[2]), "=r"(r[3]) : "r"(a));
}
__device__ __forceinline__ void mma_16816(float* c, const unsigned* a, const unsigned* b) {
    asm volatile("mma.sync.aligned.m16n8k16.row.col.f32.f16.f16.f32 "
        "{%0,%1,%2,%3}, {%4,%5,%6,%7}, {%8,%9}, {%0,%1,%2,%3};"
        : "+f"(c[0]), "+f"(c[1]), "+f"(c[2]), "+f"(c[3])
        : "r"(a[0]), "r"(a[1]), "r"(a[2]), "r"(a[3]), "r"(b[0]), "r"(b[1]));
}
__device__ __forceinline__ void cp16(unsigned d, const void* s) {
    asm volatile("cp.async.cg.shared.global [%0], [%1], 16;" :: "r"(d), "l"(s));
}

__device__ __forceinline__ void load_W(unsigned sb, int kc, int slot, int v0,
                                       int nrows, int tid) {
    const __half* g = d_Whi + ((size_t)kc * VP + v0) * 16;
    unsigned dst = sb + SW_OFF + slot * WBUFB;
    #pragma unroll
    for (int r = 0; r < 3; r++) {
        int t = tid + r * 256;
        int row = t >> 1, hf = t & 1;
        if (row < nrows)
            cp16(dst + row * (WST * 2) + hf * 16, g + (size_t)row * 16 + hf * 8);
    }
}

__global__ void __launch_bounds__(256, 2)
logits1_k(const float* __restrict__ outb) {
    extern __shared__ __align__(16) char smem[];
    unsigned sb = cvta_s(smem);
    __half* sA = (__half*)smem;
    int tid = threadIdx.x, warp = tid >> 5, lane = tid & 31;
    int bid = blockIdx.x;

    // variable tiles: blocks 0..83 -> 6 units of 64 cols, 84..295 -> 5 units
    int nu = (bid < 84) ? 6 : 5;
    int u0 = (bid < 84) ? bid * 6 : 84 * 6 + (bid - 84) * 5;
    int v0 = u0 * 64;
    int nrows = nu * 64;

    load_W(sb, 0, 0, v0, nrows, tid);
    asm volatile("cp.async.commit_group;" ::: "memory");

    // stage A (h fp16) 64 x 320 halfs, row stride SA_STR
    for (int i = tid; i < 64 * (KP / 8); i += 256) {
        int b = i / (KP / 8), q = i - b * (KP / 8);
        uint4 val = ((const uint4*)d_hhi)[(size_t)b * (KP / 8) + q];
        *(uint4*)(sA + b * SA_STR + q * 8) = val;
    }

    float acc[4][NUMAX][4];
    #pragma unroll
    for (int mi = 0; mi < 4; mi++)
        #pragma unroll
        for (int nt = 0; nt < NUMAX; nt++)
            #pragma unroll
            for (int q = 0; q < 4; q++) acc[mi][nt][q] = 0.f;

    int wn = warp * nu * 8;   // warp's col base within tile (nu n-tiles of 8)
    int buf = 0;
    for (int c = 0; c < NCHUNK; c++) {
        if (c + 1 < NCHUNK) {
            load_W(sb, c + 1, buf ^ 1, v0, nrows, tid);
            asm volatile("cp.async.commit_group;" ::: "memory");
            asm volatile("cp.async.wait_group 1;" ::: "memory");
        } else {
            asm volatile("cp.async.wait_group 0;" ::: "memory");
        }
        __syncthreads();

        int k0 = c * 16;
        unsigned a[4][4];
        #pragma unroll
        for (int mi = 0; mi < 4; mi++) {
            int rowA = mi * 16 + (lane & 15);
            int colA = k0 + ((lane >> 4) << 3);
            ldsm_x4(a[mi], sb + (rowA * SA_STR + colA) * 2);
        }
        unsigned wbase = sb + SW_OFF + buf * WBUFB;
        unsigned bf[3][4];
        #pragma unroll
        for (int pr = 0; pr < 3; pr++) {
            int rowB = wn + pr * 16 + ((lane & 7) | (((lane >> 4) & 1) << 3));
            int colB = ((lane >> 3) & 1) * 8;
            ldsm_x4(bf[pr], wbase + (rowB * WST + colB) * 2);
        }
        #pragma unroll
        for (int mi = 0; mi < 4; mi++)
            #pragma unroll
            for (int nt = 0; nt < NUMAX; nt++)
                if (nt < nu)
                    mma_16816(acc[mi][nt], a[mi], &bf[nt >> 1][(nt & 1) * 2]);
        __syncthreads();
        buf ^= 1;
    }

    // ---- epilogue: bias + fp16 stores of approx logits ----
    #pragma unroll
    for (int nt = 0; nt < NUMAX; nt++) {
        if (nt < nu) {
            int v = v0 + wn + nt * 8 + (lane & 3) * 2;
            float bias0 = (v < V)     ? outb[v]     : -1e4f;
            float bias1 = (v + 1 < V) ? outb[v + 1] : -1e4f;
            #pragma unroll
            for (int mi = 0; mi < 4; mi++) {
                int r1 = mi * 16 + (lane >> 2);
                int r2 = r1 + 8;
                float f00 = acc[mi][nt][0] + bias0, f01 = acc[mi][nt][1] + bias1;
                float f10 = acc[mi][nt][2] + bias0, f11 = acc[mi][nt][3] + bias1;
                *(__half2*)(d_alog + (size_t)r1 * VP + v) = __floats2half2_rn(f00, f01);
                *(__half2*)(d_alog + (size_t)r2 * VP + v) = __floats2half2_rn(f10, f11);
            }
        }
    }
}

// ================= logits pass 2: one block per batch row =================
__global__ void __launch_bounds__(512, 2)
scan_k(const float* __restrict__ outW, const float* __restrict__ outb,
       float* __restrict__ out, int t, int p) {
    __shared__ float smaxs[16];
    __shared__ unsigned long long sbest[16];
    __shared__ float hs[304];
    __shared__ float thr;
    int b = blockIdx.x;
    int tid = threadIdx.x, lane = tid & 31, warp = tid >> 5;
    const __half* arow = d_alog + (size_t)b * VP;
    const float* hrow = (p ? d_h0 : d_h1) + b * H;

    if (tid < H) hs[tid] = hrow[tid];

    // phase A: block max of stored fp16 approx logits
    float mx = -3e38f;
    for (int i = tid; i < VP / 8; i += 512) {
        uint4 pk = ((const uint4*)arow)[i];
        __half hv[8];
        *(uint4*)hv = pk;
        #pragma unroll
        for (int j = 0; j < 8; j++) mx = fmaxf(mx, __half2float(hv[j]));
    }
    #pragma unroll
    for (int o = 16; o; o >>= 1) mx = fmaxf(mx, __shfl_xor_sync(0xffffffffu, mx, o));
    if (lane == 0) smaxs[warp] = mx;
    __syncthreads();
    if (tid == 0) {
        float m2 = smaxs[0];
        #pragma unroll
        for (int w = 1; w < 16; w++) m2 = fmaxf(m2, smaxs[w]);
        thr = m2 - 0.09f;
    }
    __syncthreads();
    float th = thr;

    // phase B: candidates + exact fp32 rescore
    unsigned long long best = 0ULL;
    for (int i = tid; i < VP / 8; i += 512) {
        uint4 pk = ((const uint4*)arow)[i];
        __half hv[8];
        *(uint4*)hv = pk;
        #pragma unroll
        for (int j = 0; j < 8; j++) {
            float f = __half2float(hv[j]);
            int v = i * 8 + j;
            if (f >= th && v < V) {
                float s = outb[v];
                const float* wr = outW + (size_t)v * H;
                for (int k = 0; k < H; k += 4) {
                    float4 w4 = *(const float4*)(wr + k);
                    s += hs[k] * w4.x + hs[k + 1] * w4.y + hs[k + 2] * w4.z + hs[k + 3] * w4.w;
                }
                best = umax64(best, pack_key(s, v));
            }
        }
    }
    #pragma unroll
    for (int o = 16; o; o >>= 1) best = umax64(best, __shfl_xor_sync(0xffffffffu, best, o));
    if (lane == 0) sbest[warp] = best;
    __syncthreads();
    if (tid == 0) {
        unsigned long long m = sbest[0];
        #pragma unroll
        for (int w = 1; w < 16; w++) m = umax64(m, sbest[w]);
        int idx = (int)(0xFFFFFFFFu - (unsigned)(m & 0xFFFFFFFFULL));
        d_ids[b] = idx;
        out[t * B + b] = (float)idx;
    }
}

// ---------------- launch ----------------
extern "C" void kernel_launch(void* const* d_in, const int* in_sizes, int n_in,
                              void* d_out, int out_size)
{
    const int*   input = (const int*)  d_in[0];
    const float* emb   = (const float*)d_in[1];
    const float* eWih  = (const float*)d_in[2];
    const float* eWhh  = (const float*)d_in[3];
    const float* ebih  = (const float*)d_in[4];
    const float* ebhh  = (const float*)d_in[5];
    const float* dWih  = (const float*)d_in[6];
    const float* dWhh  = (const float*)d_in[7];
    const float* dbih  = (const float*)d_in[8];
    const float* dbhh  = (const float*)d_in[9];
    const float* outW  = (const float*)d_in[10];
    const float* outb  = (const float*)d_in[11];
    float* out = (float*)d_out;

    cudaFuncSetAttribute(logits1_k, cudaFuncAttributeMaxDynamicSharedMemorySize, P1_SMEM);

    init_k<<<(B * KP + 255) / 256, 256>>>();
    {
        size_t tot = (size_t)NCHUNK * VP * 16;
        prep_w<<<(int)((tot + 255) / 256), 256>>>(outW);
    }
    prep_wt<<<dim3(1200, 4), 256>>>(eWih, eWhh, dWih, dWhh);
    enc_gi_all<<<dim3(4, 256), 256>>>(input, emb);

    // ---- encoder ----
    for (int t = 0; t < LL; t++) {
        int p = t & 1;
        enc_gh<<<dim3(4, 16), 256>>>(p);
        combine_k<<<(B * H + 255) / 256, 256>>>(1, t, ebih, ebhh, p, 0);
    }
    // ---- decoder ----
    for (int t = 0; t < LL; t++) {
        int p = t & 1;
        dec_gemm<<<dim3(4, 16, 2), 256>>>(emb, p);
        combine_k<<<(B * H + 255) / 256, 256>>>(0, 0, dbih, dbhh, p, 1);
        logits1_k<<<NBLK, 256, P1_SMEM>>>(outb);
        scan_k<<<B, 512>>>(outW, outb, out, t, p);
    }
}